// round 15
// baseline (speedup 1.0000x reference)
#include <cuda_runtime.h>
#include <cuda_fp16.h>
#include <cstdint>

// STFT via hop-polyphase + one radix-2 DIT level + freq-domain hann.
//   E_k, O_k = 256-pt DFTs (1024-periodic) of even/odd samples, same weights.
//   U_k = E_k + w^k O_k, k=0..512; U_{1024-k} = conj(E_k - w^k O_k).
//   GEMM: CTA 64m x 128j, K=256, dual acc (E,O), warp tile 32x32, U fp16.
//   Combine: X_t[k] = sum_q (-i)^{kq} U_{t+q}[k]; F = 0.5X - 0.25(X[k-1]+X[k+1]).
//   NOTE: out pitch NT=513 is odd -> vectorized direct STG is misaligned;
//   stores MUST go through the smem re-coalescing bounce (or be scalar).

#define KF     1025
#define NBC    32
#define LEN    262144
#define NT     513
#define NSEG   516
#define NJ     (NBC * NSEG)      // 16512
#define MROWSA 1152
#define KHALF  256
#define NITER  4                 // KHALF / 64
#define IMAG_OFF 16826400L

__device__ __half g_A[(size_t)MROWSA * KHALF];
__device__ __half g_B[(size_t)NJ * 512];        // [j][c]: c<256 even, else odd
__device__ __half g_Uh[(size_t)2050 * NJ + 32]; // rows 0..1024 re, 1025..2049 im (+pad)
__device__ float  g_cos_tab[2048];
__device__ float  g_msin_tab[2048];

#define SW128(b) ((b) ^ (((b) >> 3) & 0x70))

// ============================ fused prep: pack_b + pack_a + tables ============================
#define PREP_PB (NJ / 2)          // 8256
#define PREP_PA 576
#define PREP_GRID (PREP_PB + PREP_PA + 8)

__global__ void prep_kernel(const float* __restrict__ x) {
    const int b = blockIdx.x;
    const int tid = threadIdx.x;
    if (b < PREP_PB) {
        int j  = 2 * b + (tid >> 7);
        int bc = j / NSEG;
        int s  = j - bc * NSEG;
        const float* xbc = x + (size_t)bc * LEN;
        __half* bj = g_B + (size_t)j * 512;
        int c4 = tid & 127;
        int p0 = s * 512 - 1024 + 4 * c4;
        float4 v;
        if (s >= 2 && s <= 513) {
            v = *(const float4*)(xbc + p0);
        } else {
            float tmp[4];
#pragma unroll
            for (int e = 0; e < 4; ++e) {
                int p = p0 + e;
                if (p < 0) p = -p;
                if (p >= LEN) p = 2 * LEN - 2 - p;
                tmp[e] = xbc[p];
            }
            v = make_float4(tmp[0], tmp[1], tmp[2], tmp[3]);
        }
        *(__half2*)&bj[2 * c4]       = __floats2half2_rn(v.x, v.z);
        *(__half2*)&bj[256 + 2 * c4] = __floats2half2_rn(v.y, v.w);
    } else if (b < PREP_PB + PREP_PA) {
        int idx2 = ((b - PREP_PB) * 256 + tid) * 2;
        int m = idx2 >> 8;
        int c = idx2 & 255;
        __half o[2];
        if (m < 1026) {
            int k = m >> 1;
            if (m & 1) {
                o[0] = __float2half_rn(-sinpif((float)((2 * k * c) & 2047) * (1.0f / 1024.0f)));
                o[1] = __float2half_rn(-sinpif((float)((2 * k * (c + 1)) & 2047) * (1.0f / 1024.0f)));
            } else {
                o[0] = __float2half_rn(cospif((float)((2 * k * c) & 2047) * (1.0f / 1024.0f)));
                o[1] = __float2half_rn(cospif((float)((2 * k * (c + 1)) & 2047) * (1.0f / 1024.0f)));
            }
        } else {
            o[0] = o[1] = __float2half_rn(0.f);
        }
        *(__half2*)&g_A[(size_t)m * KHALF + c] = *(__half2*)o;
    } else {
        int i = (b - PREP_PB - PREP_PA) * 256 + tid;
        float a = (float)i * (1.0f / 1024.0f);
        g_cos_tab[i]  = cospif(a);
        g_msin_tab[i] = -sinpif(a);
    }
}

// ============================ GEMM (mma.sync fp16, dual-acc E/O) ============================
#define CP16(dst, src) \
    asm volatile("cp.async.cg.shared.global [%0], [%1], 16;" :: "r"(dst), "l"(src))
#define CP_COMMIT() asm volatile("cp.async.commit_group;" ::: "memory")
#define CP_WAIT1()  asm volatile("cp.async.wait_group 1;" ::: "memory")
#define CP_WAIT0()  asm volatile("cp.async.wait_group 0;" ::: "memory")

__device__ __forceinline__ uint32_t smem_u32(const void* p) {
    uint32_t a;
    asm("{ .reg .u64 t; cvta.to.shared.u64 t, %1; cvt.u32.u64 %0, t; }"
        : "=r"(a) : "l"(p));
    return a;
}
__device__ __forceinline__ void ldsm4(uint32_t* r, uint32_t addr) {
    asm volatile("ldmatrix.sync.aligned.m8n8.x4.shared.b16 {%0,%1,%2,%3}, [%4];"
                 : "=r"(r[0]), "=r"(r[1]), "=r"(r[2]), "=r"(r[3]) : "r"(addr));
}
__device__ __forceinline__ void mma16816(float* d, const uint32_t* a, const uint32_t* b) {
    asm volatile(
        "mma.sync.aligned.m16n8k16.row.col.f32.f16.f16.f32 "
        "{%0,%1,%2,%3},{%4,%5,%6,%7},{%8,%9},{%0,%1,%2,%3};"
        : "+f"(d[0]), "+f"(d[1]), "+f"(d[2]), "+f"(d[3])
        : "r"(a[0]), "r"(a[1]), "r"(a[2]), "r"(a[3]), "r"(b[0]), "r"(b[1]));
}

#define A_BYTES    8192
#define BT_BYTES   16384
#define STAGE_BYTES 40960
#define GEMM_SMEM  (2 * STAGE_BYTES)

__global__ void __launch_bounds__(256, 2) gemm_mma_kernel() {
    extern __shared__ char smem[];
    const int tid = threadIdx.x;
    const int wid = tid >> 5;
    const int lane = tid & 31;
    const int m0 = blockIdx.y * 64;
    const int j0 = blockIdx.x * 128;

    const uint32_t sbase = smem_u32(smem);

    uint32_t aoff[2], boff[4];
    const __half* gAp[2];
    const __half* gBep[4];
    const __half* gBop[4];
#pragma unroll
    for (int q = 0; q < 2; ++q) {
        int chunk = tid + q * 256;
        int row = chunk >> 3, slot = chunk & 7;
        aoff[q] = SW128((uint32_t)row * 128 + slot * 16);
        gAp[q] = g_A + (size_t)(m0 + row) * KHALF + slot * 8;
    }
#pragma unroll
    for (int q = 0; q < 4; ++q) {
        int chunk = tid + q * 256;
        int row = chunk >> 3, slot = chunk & 7;
        boff[q] = SW128((uint32_t)row * 128 + slot * 16);
        gBep[q] = g_B + (size_t)(j0 + row) * 512 + slot * 8;
        gBop[q] = gBep[q] + 256;
    }

#define ISSUE_LOAD(it, buf) do {                                               \
    uint32_t _b = sbase + (buf) * STAGE_BYTES;                                 \
    _Pragma("unroll")                                                          \
    for (int q = 0; q < 2; ++q) CP16(_b + aoff[q], gAp[q] + (it) * 64);        \
    _Pragma("unroll")                                                          \
    for (int q = 0; q < 4; ++q) {                                              \
        CP16(_b + A_BYTES + boff[q],            gBep[q] + (it) * 64);          \
        CP16(_b + A_BYTES + BT_BYTES + boff[q], gBop[q] + (it) * 64);          \
    }                                                                          \
} while (0)

    const int wm = wid >> 2;
    const int wn = wid & 3;
    const int arow = wm * 32 + (lane & 15);
    const int abyt = (lane >> 4) * 16;
    const int brow = wn * 32 + ((lane >> 4) << 3) + (lane & 7);
    const int bbyt = ((lane >> 3) & 1) * 16;

    float accE[2][4][4], accO[2][4][4];
#pragma unroll
    for (int i = 0; i < 2; ++i)
#pragma unroll
        for (int jt = 0; jt < 4; ++jt)
#pragma unroll
            for (int e = 0; e < 4; ++e) { accE[i][jt][e] = 0.f; accO[i][jt][e] = 0.f; }

    ISSUE_LOAD(0, 0); CP_COMMIT();
    ISSUE_LOAD(1, 1); CP_COMMIT();

    for (int it = 0; it < NITER; ++it) {
        if (it < NITER - 1) CP_WAIT1(); else CP_WAIT0();
        __syncthreads();

        const uint32_t bA = sbase + (it & 1) * STAGE_BYTES;
        const uint32_t bE = bA + A_BYTES;
        const uint32_t bO = bE + BT_BYTES;
#pragma unroll
        for (int s = 0; s < 4; ++s) {
            uint32_t a[2][4], be[2][4], bo[2][4];
#pragma unroll
            for (int i = 0; i < 2; ++i)
                ldsm4(a[i], bA + SW128((uint32_t)(arow + i * 16) * 128 + s * 32 + abyt));
#pragma unroll
            for (int p = 0; p < 2; ++p) {
                ldsm4(be[p], bE + SW128((uint32_t)(brow + p * 16) * 128 + s * 32 + bbyt));
                ldsm4(bo[p], bO + SW128((uint32_t)(brow + p * 16) * 128 + s * 32 + bbyt));
            }
#pragma unroll
            for (int i = 0; i < 2; ++i) {
#pragma unroll
                for (int p = 0; p < 2; ++p) {
                    mma16816(accE[i][2 * p],     a[i], &be[p][0]);
                    mma16816(accE[i][2 * p + 1], a[i], &be[p][2]);
                    mma16816(accO[i][2 * p],     a[i], &bo[p][0]);
                    mma16816(accO[i][2 * p + 1], a[i], &bo[p][2]);
                }
            }
        }

        __syncthreads();
        if (it + 2 < NITER) { ISSUE_LOAD(it + 2, it & 1); CP_COMMIT(); }
    }

    // ---- epilogue: stage E,O to smem (64x132 each), butterfly, fp16 stores ----
    float* smE = (float*)smem;
    float* smO = smE + 64 * 132;
    {
        const int r0 = wm * 32 + (lane >> 2);
        const int c0 = wn * 32 + (lane & 3) * 2;
#pragma unroll
        for (int i = 0; i < 2; ++i) {
            int r = r0 + i * 16;
#pragma unroll
            for (int jt = 0; jt < 4; ++jt) {
                int c = c0 + jt * 8;
                smE[r * 132 + c]           = accE[i][jt][0];
                smE[r * 132 + c + 1]       = accE[i][jt][1];
                smE[(r + 8) * 132 + c]     = accE[i][jt][2];
                smE[(r + 8) * 132 + c + 1] = accE[i][jt][3];
                smO[r * 132 + c]           = accO[i][jt][0];
                smO[r * 132 + c + 1]       = accO[i][jt][1];
                smO[(r + 8) * 132 + c]     = accO[i][jt][2];
                smO[(r + 8) * 132 + c + 1] = accO[i][jt][3];
            }
        }
    }
    __syncthreads();

    const int jl = lane * 4;
    const size_t jg = (size_t)j0 + jl;
#pragma unroll
    for (int h = 0; h < 4; ++h) {
        int kloc = wid * 4 + h;
        int kg = (m0 >> 1) + kloc;
        if (kg > 512) break;
        float4 er  = *(float4*)&smE[(2 * kloc) * 132 + jl];
        float4 ei  = *(float4*)&smE[(2 * kloc + 1) * 132 + jl];
        float4 o_r = *(float4*)&smO[(2 * kloc) * 132 + jl];
        float4 oi  = *(float4*)&smO[(2 * kloc + 1) * 132 + jl];
        float cw = g_cos_tab[kg];
        float sw = g_msin_tab[kg];

        float prx = cw * o_r.x - sw * oi.x, pix = cw * oi.x + sw * o_r.x;
        float pry = cw * o_r.y - sw * oi.y, piy = cw * oi.y + sw * o_r.y;
        float prz = cw * o_r.z - sw * oi.z, piz = cw * oi.z + sw * o_r.z;
        float prw = cw * o_r.w - sw * oi.w, piw = cw * oi.w + sw * o_r.w;

        __half2 ur_lo = __floats2half2_rn(er.x + prx, er.y + pry);
        __half2 ur_hi = __floats2half2_rn(er.z + prz, er.w + prw);
        __half2 ui_lo = __floats2half2_rn(ei.x + pix, ei.y + piy);
        __half2 ui_hi = __floats2half2_rn(ei.z + piz, ei.w + piw);
        __half2 vr_lo = __floats2half2_rn(er.x - prx, er.y - pry);
        __half2 vr_hi = __floats2half2_rn(er.z - prz, er.w - prw);
        __half2 vi_lo = __floats2half2_rn(pix - ei.x, piy - ei.y);
        __half2 vi_hi = __floats2half2_rn(piz - ei.z, piw - ei.w);

        int k2 = 1024 - kg;
        *(__half2*)(g_Uh + (size_t)kg * NJ + jg)            = ur_lo;
        *(__half2*)(g_Uh + (size_t)kg * NJ + jg + 2)        = ur_hi;
        *(__half2*)(g_Uh + (size_t)(KF + kg) * NJ + jg)     = ui_lo;
        *(__half2*)(g_Uh + (size_t)(KF + kg) * NJ + jg + 2) = ui_hi;
        *(__half2*)(g_Uh + (size_t)k2 * NJ + jg)            = vr_lo;
        *(__half2*)(g_Uh + (size_t)k2 * NJ + jg + 2)        = vr_hi;
        *(__half2*)(g_Uh + (size_t)(KF + k2) * NJ + jg)     = vi_lo;
        *(__half2*)(g_Uh + (size_t)(KF + k2) * NJ + jg + 2) = vi_hi;
    }
}

// ============================ combine (8 t's per lane, shfl halo, smem bounce) ============================
__global__ void __launch_bounds__(128) combine7_kernel(float* __restrict__ out) {
    __shared__ float sfr[4][2][256];
    __shared__ float sfi[4][2][256];
    const int bc   = blockIdx.z;
    const int lane = threadIdx.x;
    const int ty   = threadIdx.y;
    const int tbase = blockIdx.x * 256;       // 0, 256, 512
    const int kb   = (blockIdx.y * 4 + ty) * 32;
    if (kb > 1024) return;

    const bool full = (tbase < 512);          // blocks 0,1: max t = tbase+255 <= 511
    const int t8  = tbase + lane * 8;
    const int tt8 = full ? t8 : 512;          // boundary block: all lanes load at t=512
    const size_t jj = (size_t)bc * NSEG + tt8;
    const long baseT = (long)bc * KF;

    float pXr0[8], pXr1[8], pXi0[8], pXi1[8];
#pragma unroll
    for (int e = 0; e < 8; ++e) { pXr0[e] = pXr1[e] = pXi0[e] = pXi1[e] = 0.f; }

    for (int i = 0; i < 34; ++i) {
        int k = kb - 1 + i;
        int kk = k;
        float sgn = 1.f;
        if (kk < 0)         { kk = -kk;       sgn = -1.f; }
        else if (kk > 1024) { kk = 2048 - kk; sgn = -1.f; }

        const __half* pr = g_Uh + (size_t)kk * NJ + jj;
        const __half* pi = g_Uh + (size_t)(KF + kk) * NJ + jj;
        uint2 r0v = *(const uint2*)pr;        // t8 .. t8+3
        uint2 r1v = *(const uint2*)(pr + 4);  // t8+4 .. t8+7
        uint2 i0v = *(const uint2*)pi;
        uint2 i1v = *(const uint2*)(pi + 4);
        uint2 rh, ih;                         // halo: t8+8 .. t8+11
        rh.x = __shfl_down_sync(0xffffffffu, r0v.x, 1);
        rh.y = __shfl_down_sync(0xffffffffu, r0v.y, 1);
        ih.x = __shfl_down_sync(0xffffffffu, i0v.x, 1);
        ih.y = __shfl_down_sync(0xffffffffu, i0v.y, 1);
        if (lane == 31) {
            rh = *(const uint2*)(pr + 8);
            ih = *(const uint2*)(pi + 8);
        }

        float rr[12], ii[12];
        {
            float2 f;
            f = __half22float2(*(__half2*)&r0v.x); rr[0] = f.x; rr[1] = f.y;
            f = __half22float2(*(__half2*)&r0v.y); rr[2] = f.x; rr[3] = f.y;
            f = __half22float2(*(__half2*)&r1v.x); rr[4] = f.x; rr[5] = f.y;
            f = __half22float2(*(__half2*)&r1v.y); rr[6] = f.x; rr[7] = f.y;
            f = __half22float2(*(__half2*)&rh.x);  rr[8] = f.x; rr[9] = f.y;
            f = __half22float2(*(__half2*)&rh.y);  rr[10] = f.x; rr[11] = f.y;
            f = __half22float2(*(__half2*)&i0v.x); ii[0] = f.x; ii[1] = f.y;
            f = __half22float2(*(__half2*)&i0v.y); ii[2] = f.x; ii[3] = f.y;
            f = __half22float2(*(__half2*)&i1v.x); ii[4] = f.x; ii[5] = f.y;
            f = __half22float2(*(__half2*)&i1v.y); ii[6] = f.x; ii[7] = f.y;
            f = __half22float2(*(__half2*)&ih.x);  ii[8] = f.x; ii[9] = f.y;
            f = __half22float2(*(__half2*)&ih.y);  ii[10] = f.x; ii[11] = f.y;
        }

        float xr[8], xi[8];
        switch (kk & 3) {
            case 0:
#pragma unroll
                for (int e = 0; e < 8; ++e) {
                    xr[e] = rr[e] + rr[e+1] + rr[e+2] + rr[e+3];
                    xi[e] = sgn * (ii[e] + ii[e+1] + ii[e+2] + ii[e+3]);
                }
                break;
            case 1:
#pragma unroll
                for (int e = 0; e < 8; ++e) {
                    xr[e] = rr[e] + ii[e+1] - rr[e+2] - ii[e+3];
                    xi[e] = sgn * (ii[e] - rr[e+1] - ii[e+2] + rr[e+3]);
                }
                break;
            case 2:
#pragma unroll
                for (int e = 0; e < 8; ++e) {
                    xr[e] = rr[e] - rr[e+1] + rr[e+2] - rr[e+3];
                    xi[e] = sgn * (ii[e] - ii[e+1] + ii[e+2] - ii[e+3]);
                }
                break;
            default:
#pragma unroll
                for (int e = 0; e < 8; ++e) {
                    xr[e] = rr[e] - ii[e+1] - rr[e+2] + ii[e+3];
                    xi[e] = sgn * (ii[e] + rr[e+1] - ii[e+2] - rr[e+3]);
                }
                break;
        }

        if (i >= 2) {
            const int ko = k - 1;
            if (ko <= 1024) {
                const long baseR = (baseT + ko) * NT;
                float vr[8], vi[8];
#pragma unroll
                for (int e = 0; e < 8; ++e) {
                    vr[e] = 0.5f * pXr1[e] - 0.25f * (pXr0[e] + xr[e]);
                    vi[e] = 0.5f * pXi1[e] - 0.25f * (pXi0[e] + xi[e]);
                }
                if (full) {
                    const int buf = i & 1;
                    *(float4*)&sfr[ty][buf][lane * 8]     = make_float4(vr[0], vr[1], vr[2], vr[3]);
                    *(float4*)&sfr[ty][buf][lane * 8 + 4] = make_float4(vr[4], vr[5], vr[6], vr[7]);
                    *(float4*)&sfi[ty][buf][lane * 8]     = make_float4(vi[0], vi[1], vi[2], vi[3]);
                    *(float4*)&sfi[ty][buf][lane * 8 + 4] = make_float4(vi[4], vi[5], vi[6], vi[7]);
                    __syncwarp();
#pragma unroll
                    for (int e = 0; e < 8; ++e) {
                        int t = tbase + 32 * e + lane;
                        out[baseR + t]            = sfr[ty][buf][32 * e + lane];
                        out[IMAG_OFF + baseR + t] = sfi[ty][buf][32 * e + lane];
                    }
                } else if (lane == 0) {
                    out[baseR + 512]            = vr[0];
                    out[IMAG_OFF + baseR + 512] = vi[0];
                }
            }
        }
#pragma unroll
        for (int e = 0; e < 8; ++e) {
            pXr0[e] = pXr1[e]; pXr1[e] = xr[e];
            pXi0[e] = pXi1[e]; pXi1[e] = xi[e];
        }
    }
}

// ============================ launch ============================
extern "C" void kernel_launch(void* const* d_in, const int* in_sizes, int n_in,
                              void* d_out, int out_size)
{
    const float* x = (const float*)d_in[0];
    float* out = (float*)d_out;

    cudaFuncSetAttribute(gemm_mma_kernel,
                         cudaFuncAttributeMaxDynamicSharedMemorySize, GEMM_SMEM);

    prep_kernel<<<PREP_GRID, 256>>>(x);
    gemm_mma_kernel<<<dim3(NJ / 128, 17), 256, GEMM_SMEM>>>();
    combine7_kernel<<<dim3(3, 9, NBC), dim3(32, 4)>>>(out);
}